// round 16
// baseline (speedup 1.0000x reference)
#include <cuda_runtime.h>
#include <cuda_bf16.h>
#include <math.h>
#include <stdint.h>

#define D_MODEL 1024
#define NHEAD   16
#define HDIM    64
#define SEQ     2048
#define BATCH   2
#define MTOT    (BATCH * SEQ)   // 4096
#define KP      3072            // split-bf16 K' = 3*1024
#define TK      64              // bf16 per K chunk (128 bytes)
#define NC      (KP / TK)       // 48 chunks
#define LOG2E   1.4426950408889634f

// ---------------- scratch (static device globals: allocation-free) ----------
__device__ float g_K[BATCH * NHEAD * SEQ * HDIM];   // [b,h,s,d] fp32
__device__ float g_V[BATCH * NHEAD * SEQ * HDIM];
__device__ __nv_bfloat16 g_Ax[MTOT * KP];           // split x    (A-mode)
__device__ __nv_bfloat16 g_Bqkv[3 * D_MODEL * KP];  // split Wq|Wk|Wv (B-mode)
__device__ __nv_bfloat16 g_Bo[D_MODEL * KP];
__device__ __nv_bfloat16 g_Aatt[MTOT * KP];         // split attn out (A-mode)
// attention operands, preconverted:
__device__ __nv_bfloat16 g_Qp[32 * SEQ * 128];          // [bh*2048+s][qh|ql]
__device__ __nv_bfloat16 g_Kp[32 * 32 * 64 * 128];      // [bh][kt] 16KB swizzled
__device__ __nv_bfloat16 g_Vp[32 * 32 * 64 * 128];      // [bh][kt] 16KB swizzled

// ============================ helpers ========================================
__device__ __forceinline__ uint32_t smem_u32(const void* p) {
    uint32_t a;
    asm("{ .reg .u64 t; cvta.to.shared.u64 t, %1; cvt.u32.u64 %0, t; }"
        : "=r"(a) : "l"(p));
    return a;
}
__device__ __forceinline__ void ldsm4(uint32_t* r, uint32_t addr) {
    asm volatile("ldmatrix.sync.aligned.m8n8.x4.shared.b16 {%0,%1,%2,%3}, [%4];"
                 : "=r"(r[0]), "=r"(r[1]), "=r"(r[2]), "=r"(r[3]) : "r"(addr));
}
__device__ __forceinline__ void mma16816(float* d, const uint32_t* a,
                                         const uint32_t* b) {
    asm volatile(
        "mma.sync.aligned.m16n8k16.row.col.f32.bf16.bf16.f32 "
        "{%0,%1,%2,%3}, {%4,%5,%6,%7}, {%8,%9}, {%0,%1,%2,%3};"
        : "+f"(d[0]), "+f"(d[1]), "+f"(d[2]), "+f"(d[3])
        : "r"(a[0]), "r"(a[1]), "r"(a[2]), "r"(a[3]), "r"(b[0]), "r"(b[1]));
}
__device__ __forceinline__ void cpa16(uint32_t dst, const void* src) {
    asm volatile("cp.async.cg.shared.global [%0], [%1], 16;"
                 :: "r"(dst), "l"(src));
}
#define CP_COMMIT() asm volatile("cp.async.commit_group;")
#define CP_WAIT0()  asm volatile("cp.async.wait_group 0;")
#define CP_WAIT1()  asm volatile("cp.async.wait_group 1;")

// 2^y on the FMA pipe; clamped so -huge -> ~1e-38 (≈0)
__device__ __forceinline__ float exp2p(float y) {
    y = fmaxf(y, -126.0f);
    const int   ni = __float2int_rn(y);
    const float f  = y - (float)ni;
    float p = 0.0096181f;
    p = fmaf(p, f, 0.0555041f);
    p = fmaf(p, f, 0.2402265f);
    p = fmaf(p, f, 0.6931472f);
    p = fmaf(p, f, 1.0f);
    return __int_as_float(__float_as_int(p) + (ni << 23));
}
__device__ __forceinline__ uint32_t pack_bf2(float a, float b) {
    return ((uint32_t)__bfloat16_as_ushort(__float2bfloat16(b)) << 16)
         | __bfloat16_as_ushort(__float2bfloat16(a));
}
__device__ __forceinline__ float bhi(float x) {
    return __bfloat162float(__float2bfloat16(x));
}
// byte offset in a 256B-row (128 bf16 col) XOR-swizzled tile
__device__ __forceinline__ uint32_t sw256(int row, int col) {
    return (uint32_t)(row * 256 + ((col >> 6) << 7)
                      + ((((col >> 3) & 7) ^ (row & 7)) << 4) + (col & 7) * 2);
}

// ============================ split kernels ==================================
__device__ __forceinline__ void split_row(const float* __restrict__ src,
                                          __nv_bfloat16* __restrict__ dst,
                                          int idx, int bmode)
{
    const int row = idx >> 8;
    const int c   = (idx & 255) * 4;
    float4 v = *(const float4*)(src + (size_t)row * 1024 + c);

    __nv_bfloat16 h0 = __float2bfloat16(v.x), h1 = __float2bfloat16(v.y);
    __nv_bfloat16 h2 = __float2bfloat16(v.z), h3 = __float2bfloat16(v.w);
    uint2 hu, lu;
    hu.x = ((uint32_t)__bfloat16_as_ushort(h1) << 16) | __bfloat16_as_ushort(h0);
    hu.y = ((uint32_t)__bfloat16_as_ushort(h3) << 16) | __bfloat16_as_ushort(h2);
    lu.x = pack_bf2(v.x - __bfloat162float(h0), v.y - __bfloat162float(h1));
    lu.y = pack_bf2(v.z - __bfloat162float(h2), v.w - __bfloat162float(h3));

    __nv_bfloat16* p = dst + (size_t)row * KP + c;
    if (bmode) {
        *(uint2*)(p) = hu; *(uint2*)(p + 1024) = lu; *(uint2*)(p + 2048) = hu;
    } else {
        *(uint2*)(p) = hu; *(uint2*)(p + 1024) = hu; *(uint2*)(p + 2048) = lu;
    }
}
__global__ __launch_bounds__(256) void split_x(
    const float* __restrict__ src, __nv_bfloat16* __restrict__ dst)
{
    split_row(src, dst, blockIdx.x * 256 + threadIdx.x, 0);
}
__global__ __launch_bounds__(256) void split_w(
    const float* __restrict__ w0, const float* __restrict__ w1,
    const float* __restrict__ w2, const float* __restrict__ w3,
    __nv_bfloat16* __restrict__ dqkv, __nv_bfloat16* __restrict__ do_)
{
    const int y = blockIdx.y;
    const float* src = (y == 0) ? w0 : (y == 1) ? w1 : (y == 2) ? w2 : w3;
    __nv_bfloat16* dst = (y == 3) ? do_ : dqkv + (size_t)y * 1024 * KP;
    split_row(src, dst, blockIdx.x * 256 + threadIdx.x, 1);
}

// ====== mma.sync GEMM: 4 warps, 64x64 warp tile, 3-stage cp.async ===========
// CTA tile 128x128. mode 0: C0 fp32 row-major. mode 1: fused QKV (which=bn>>10)
#define SMEM_BYTES 98304   // 3 stages x (A 16K + B 16K)

__device__ __forceinline__ void cpa_tiles(
    const __nv_bfloat16* __restrict__ A, const __nv_bfloat16* __restrict__ B,
    int bm, int bn, int c, int tid, uint32_t sbase, uint32_t p)
{
    const uint32_t Ab = sbase + p * 32768u;
#pragma unroll
    for (int j = 0; j < 8; ++j) {
        const int idx = j * 128 + tid, r = idx >> 3, s = idx & 7;
        uint32_t off = (uint32_t)(r * 128 + s * 16);
        off ^= (off >> 3) & 0x70;
        cpa16(Ab + off,           A + (size_t)(bm + r) * KP + c * TK + s * 8);
        cpa16(Ab + 16384u + off,  B + (size_t)(bn + r) * KP + c * TK + s * 8);
    }
    CP_COMMIT();
}

__global__ __launch_bounds__(128, 2) void gemm_mma(
    const __nv_bfloat16* __restrict__ A, const __nv_bfloat16* __restrict__ B,
    void* __restrict__ C0, float* __restrict__ C1, float* __restrict__ C2,
    int mode)
{
    extern __shared__ char smem[];
    const uint32_t sbase = smem_u32(smem);
    const int tid  = threadIdx.x;
    const int warp = tid >> 5;
    const int lane = tid & 31;
    const int bm   = blockIdx.y * 128;
    const int bn   = blockIdx.x * 128;
    const int wm   = warp & 1;     // 2 warps in M
    const int wn   = warp >> 1;    // 2 warps in N (64 cols each)

    cpa_tiles(A, B, bm, bn, 0, tid, sbase, 0);
    cpa_tiles(A, B, bm, bn, 1, tid, sbase, 1);

    float acc[4][8][4];
#pragma unroll
    for (int i = 0; i < 4; ++i)
#pragma unroll
        for (int j = 0; j < 8; ++j)
#pragma unroll
            for (int r = 0; r < 4; ++r) acc[i][j][r] = 0.0f;

    const int arow = (lane & 7) | ((lane >> 3) & 1) << 3;
    const int ach  = (lane >> 4) & 1;
    uint32_t aterm[4]; int asw[4];
#pragma unroll
    for (int i = 0; i < 4; ++i) {
        const int row = wm * 64 + i * 16 + arow;
        aterm[i] = (uint32_t)(row * 128);
        asw[i]   = row & 7;
    }
    const int q   = lane >> 3;
    const int bch = q & 1;
    uint32_t bterm[4]; int bsw[4];
#pragma unroll
    for (int jj = 0; jj < 4; ++jj) {
        const int nrow = wn * 64 + jj * 16 + ((q >> 1) << 3) + (lane & 7);
        bterm[jj] = (uint32_t)(nrow * 128);
        bsw[jj]   = nrow & 7;
    }

    int p = 0;
    int pn = 2;
    for (int c = 0; c < NC; ++c) {
        if (c < NC - 1) { CP_WAIT1(); } else { CP_WAIT0(); }
        __syncthreads();

        if (c + 2 < NC) cpa_tiles(A, B, bm, bn, c + 2, tid, sbase, (uint32_t)pn);

        const uint32_t Ab = sbase + (uint32_t)(p * 32768);
        const uint32_t Bb = Ab + 16384u;

#pragma unroll
        for (int ks = 0; ks < 4; ++ks) {
            const int k2 = ks * 2;
            uint32_t af[4][4], bf[8][2];
#pragma unroll
            for (int i = 0; i < 4; ++i)
                ldsm4(af[i], Ab + aterm[i] + ((uint32_t)((k2 + ach) ^ asw[i]) << 4));
#pragma unroll
            for (int jj = 0; jj < 4; ++jj) {
                uint32_t t[4];
                ldsm4(t, Bb + bterm[jj] + ((uint32_t)((k2 + bch) ^ bsw[jj]) << 4));
                bf[jj * 2 + 0][0] = t[0]; bf[jj * 2 + 0][1] = t[1];
                bf[jj * 2 + 1][0] = t[2]; bf[jj * 2 + 1][1] = t[3];
            }
#pragma unroll
            for (int i = 0; i < 4; ++i)
#pragma unroll
                for (int j = 0; j < 8; ++j)
                    mma16816(acc[i][j], af[i], bf[j]);
        }

        p  = (p  == 2) ? 0 : p  + 1;
        pn = (pn == 2) ? 0 : pn + 1;
    }

    const int g   = lane >> 2;
    const int tig = lane & 3;
    const int which = (mode == 1) ? (bn >> 10) : 0;
#pragma unroll
    for (int i = 0; i < 4; ++i) {
#pragma unroll
        for (int j = 0; j < 8; ++j) {
            const int col = bn + wn * 64 + j * 8 + tig * 2;
            const int m0  = bm + wm * 64 + i * 16 + g;
#pragma unroll
            for (int hrow = 0; hrow < 2; ++hrow) {
                const int m = m0 + hrow * 8;
                float v0 = acc[i][j][hrow * 2];
                float v1 = acc[i][j][hrow * 2 + 1];
                if (mode == 0) {
                    *(float2*)((float*)C0 + (size_t)m * D_MODEL + col) =
                        make_float2(v0, v1);
                    continue;
                }
                const int b = m >> 11, s2 = m & 2047;
                const int cq = col & 1023;
                const int h = cq >> 6, dd = cq & 63;
                if (which == 0) {
                    v0 *= 0.125f; v1 *= 0.125f;
                    const __nv_bfloat16 h0 = __float2bfloat16(v0);
                    const __nv_bfloat16 h1 = __float2bfloat16(v1);
                    const uint32_t hu = ((uint32_t)__bfloat16_as_ushort(h1) << 16)
                                      | __bfloat16_as_ushort(h0);
                    const uint32_t lu = pack_bf2(v0 - __bfloat162float(h0),
                                                 v1 - __bfloat162float(h1));
                    __nv_bfloat16* qp = (__nv_bfloat16*)C0
                        + ((size_t)(b * NHEAD + h) * SEQ + s2) * 128;
                    *(uint32_t*)(qp + dd)      = hu;
                    *(uint32_t*)(qp + 64 + dd) = lu;
                } else {
                    float* Cx = (which == 1) ? C1 : C2;
                    *(float2*)(Cx + ((((size_t)b * NHEAD + h) * SEQ + s2) * HDIM + dd)) =
                        make_float2(v0, v1);
                }
            }
        }
    }
}

// =================== fused K'/V' pre-convert (grid.z: 0=K, 1=V) ==============
__global__ __launch_bounds__(128) void conv_kv(const float* __restrict__ Kg,
                                               const float* __restrict__ Vg,
                                               __nv_bfloat16* __restrict__ Kp,
                                               __nv_bfloat16* __restrict__ Vp)
{
    __shared__ float ts[64][65];
    const int bh = blockIdx.y, kt = blockIdx.x, tid = threadIdx.x;
    if (blockIdx.z == 0) {
        char* dst = (char*)(Kp + ((size_t)bh * 32 + kt) * 8192);
        const int key = tid >> 1, d0 = (tid & 1) * 32;
        const float* src = Kg + (((size_t)bh * SEQ) + kt * 64 + key) * 64 + d0;
#pragma unroll
        for (int g8 = 0; g8 < 32; g8 += 8) {
            const float4 a = *(const float4*)(src + g8);
            const float4 b = *(const float4*)(src + g8 + 4);
            const __nv_bfloat16 h0 = __float2bfloat16(a.x), h1 = __float2bfloat16(a.y);
            const __nv_bfloat16 h2 = __float2bfloat16(a.z), h3 = __float2bfloat16(a.w);
            const __nv_bfloat16 h4 = __float2bfloat16(b.x), h5 = __float2bfloat16(b.y);
            const __nv_bfloat16 h6 = __float2bfloat16(b.z), h7 = __float2bfloat16(b.w);
            uint4 hu, lu;
            hu.x = ((uint32_t)__bfloat16_as_ushort(h1) << 16) | __bfloat16_as_ushort(h0);
            hu.y = ((uint32_t)__bfloat16_as_ushort(h3) << 16) | __bfloat16_as_ushort(h2);
            hu.z = ((uint32_t)__bfloat16_as_ushort(h5) << 16) | __bfloat16_as_ushort(h4);
            hu.w = ((uint32_t)__bfloat16_as_ushort(h7) << 16) | __bfloat16_as_ushort(h6);
            lu.x = pack_bf2(a.x - __bfloat162float(h0), a.y - __bfloat162float(h1));
            lu.y = pack_bf2(a.z - __bfloat162float(h2), a.w - __bfloat162float(h3));
            lu.z = pack_bf2(b.x - __bfloat162float(h4), b.y - __bfloat162float(h5));
            lu.w = pack_bf2(b.z - __bfloat162float(h6), b.w - __bfloat162float(h7));
            *(uint4*)(dst + sw256(key, d0 + g8))      = hu;
            *(uint4*)(dst + sw256(key, 64 + d0 + g8)) = lu;
        }
    } else {
        char* dst = (char*)(Vp + ((size_t)bh * 32 + kt) * 8192);
        {
            const int key = tid >> 1, d0 = (tid & 1) * 32;
            const float* src = Vg + (((size_t)bh * SEQ) + kt * 64 + key) * 64 + d0;
#pragma unroll
            for (int g4 = 0; g4 < 32; g4 += 4) {
                const float4 a = *(const float4*)(src + g4);
                ts[d0 + g4 + 0][key] = a.x;
                ts[d0 + g4 + 1][key] = a.y;
                ts[d0 + g4 + 2][key] = a.z;
                ts[d0 + g4 + 3][key] = a.w;
            }
        }
        __syncthreads();
        {
            const int d = tid >> 1, k0 = (tid & 1) * 32;
#pragma unroll
            for (int g8 = 0; g8 < 32; g8 += 8) {
                float v[8];
#pragma unroll
                for (int u = 0; u < 8; ++u) v[u] = ts[d][k0 + g8 + u];
                uint4 hu, lu;
                const __nv_bfloat16 h0 = __float2bfloat16(v[0]), h1 = __float2bfloat16(v[1]);
                const __nv_bfloat16 h2 = __float2bfloat16(v[2]), h3 = __float2bfloat16(v[3]);
                const __nv_bfloat16 h4 = __float2bfloat16(v[4]), h5 = __float2bfloat16(v[5]);
                const __nv_bfloat16 h6 = __float2bfloat16(v[6]), h7 = __float2bfloat16(v[7]);
                hu.x = ((uint32_t)__bfloat16_as_ushort(h1) << 16) | __bfloat16_as_ushort(h0);
                hu.y = ((uint32_t)__bfloat16_as_ushort(h3) << 16) | __bfloat16_as_ushort(h2);
                hu.z = ((uint32_t)__bfloat16_as_ushort(h5) << 16) | __bfloat16_as_ushort(h4);
                hu.w = ((uint32_t)__bfloat16_as_ushort(h7) << 16) | __bfloat16_as_ushort(h6);
                lu.x = pack_bf2(v[0] - __bfloat162float(h0), v[1] - __bfloat162float(h1));
                lu.y = pack_bf2(v[2] - __bfloat162float(h2), v[3] - __bfloat162float(h3));
                lu.z = pack_bf2(v[4] - __bfloat162float(h4), v[5] - __bfloat162float(h5));
                lu.w = pack_bf2(v[6] - __bfloat162float(h6), v[7] - __bfloat162float(h7));
                *(uint4*)(dst + sw256(d, k0 + g8))      = hu;
                *(uint4*)(dst + sw256(d, 64 + k0 + g8)) = lu;
            }
        }
    }
}

// ======================= FA2 tensor-core attention (R12, validated) ==========
__device__ __forceinline__ void bpass(
    float acc[8][4], const uint32_t a[4][4], uint32_t bufu, int segcol,
    int rbase, int bch)
{
#pragma unroll
    for (int t = 0; t < 4; ++t) {
        uint32_t bf[8][2];
#pragma unroll
        for (int jj = 0; jj < 4; ++jj) {
            uint32_t bt[4];
            ldsm4(bt, bufu + sw256(jj * 16 + rbase, segcol + t * 16 + bch * 8));
            bf[jj * 2 + 0][0] = bt[0]; bf[jj * 2 + 0][1] = bt[1];
            bf[jj * 2 + 1][0] = bt[2]; bf[jj * 2 + 1][1] = bt[3];
        }
#pragma unroll
        for (int j = 0; j < 8; ++j) mma16816(acc[j], a[t], bf[j]);
    }
}

__global__ __launch_bounds__(128) void attn_fa2(
    __nv_bfloat16* __restrict__ Aout,
    const __nv_bfloat16* __restrict__ Qp,
    const __nv_bfloat16* __restrict__ Kp,
    const __nv_bfloat16* __restrict__ Vp)
{
    extern __shared__ char sm[];
    const uint32_t sbase = smem_u32(sm);
    const int tid  = threadIdx.x;
    const int warp = tid >> 5;
    const int lane = tid & 31;
    const int bh   = blockIdx.y;
    const int qt   = (int)gridDim.x - 1 - (int)blockIdx.x;   // heavy first
    const int q0   = qt * 64;
    const int ktmax = qt;

    {
        const char* ksrc = (const char*)(Kp + ((size_t)bh * 32) * 8192);
        const char* vsrc = (const char*)(Vp + ((size_t)bh * 32) * 8192);
#pragma unroll
        for (int i = 0; i < 8; ++i) {
            const uint32_t off = (uint32_t)(i * 2048 + tid * 16);
            cpa16(sbase + off, ksrc + off);
            cpa16(sbase + 16384u + off, vsrc + off);
        }
        CP_COMMIT();
    }

    const uint32_t stage = sbase + 32768u;
    {
        const __nv_bfloat16* qsrc = Qp + ((size_t)bh * SEQ + q0) * 128;
#pragma unroll
        for (int i = 0; i < 8; ++i) {
            const int c    = i * 128 + tid;
            const int row  = c >> 4;
            const int col8 = (c & 15) * 8;
            const uint4 v = *(const uint4*)(qsrc + (size_t)row * 128 + col8);
            *(uint4*)(sm + 32768 + sw256(row, col8)) = v;
        }
    }
    __syncthreads();

    const int arow  = (lane & 7) | (((lane >> 3) & 1) << 3);
    const int ach   = (lane >> 4) & 1;
    const int lq    = lane >> 3;
    const int bch   = lq & 1;
    const int rbase = ((lq >> 1) << 3) + (lane & 7);
    const int g     = lane >> 2;
    const int tig   = lane & 3;

    uint32_t aQh[4][4], aQl[4][4];
#pragma unroll
    for (int t = 0; t < 4; ++t) {
        ldsm4(aQh[t], stage + sw256(warp * 16 + arow, t * 16 + ach * 8));
        ldsm4(aQl[t], stage + sw256(warp * 16 + arow, 64 + t * 16 + ach * 8));
    }

    float acc_o[8][4];
#pragma unroll
    for (int j = 0; j < 8; ++j)
#pragma unroll
        for (int r = 0; r < 4; ++r) acc_o[j][r] = 0.0f;
    float m0 = -1e30f, m1 = -1e30f, l0 = 0.0f, l1 = 0.0f;

    const int row0 = q0 + warp * 16 + g;
    const int row1 = row0 + 8;

    for (int kt = 0; kt <= ktmax; ++kt) {
        CP_WAIT0();
        __syncthreads();

        if (kt < ktmax) {
            const char* ksrc = (const char*)(Kp + ((size_t)bh * 32 + kt + 1) * 8192);
            const char* vsrc = (const char*)(Vp + ((size_t)bh * 32 + kt + 1) * 8192);
            const uint32_t dst = sbase + (uint32_t)(((kt + 1) & 1) * 32768);
#pragma unroll
            for (int i = 0; i < 8; ++i) {
                const uint32_t off = (uint32_t)(i * 2048 + tid * 16);
                cpa16(dst + off, ksrc + off);
                cpa16(dst + 16384u + off, vsrc + off);
            }
            CP_COMMIT();
        }

        const uint32_t Kb = sbase + (uint32_t)((kt & 1) * 32768);
        const uint32_t Vb = Kb + 16384u;

        float acc_s[8][4];
#pragma unroll
        for (int j = 0; j < 8; ++j)
#pragma unroll
            for (int r = 0; r < 4; ++r) acc_s[j][r] = 0.0f;
        bpass(acc_s, aQh, Kb, 0,  rbase, bch);
        bpass(acc_s, aQh, Kb, 64, rbase, bch);
        bpass(acc_s, aQl, Kb, 0,  rbase, bch);

        if (kt * 64 + 63 > row0) {
#pragma unroll
            for (int j = 0; j < 8; ++j) {
                const int col = kt * 64 + j * 8 + tig * 2;
                if (col     > row0) acc_s[j][0] = -1e30f;
                if (col + 1 > row0) acc_s[j][1] = -1e30f;
                if (col     > row1) acc_s[j][2] = -1e30f;
                if (col + 1 > row1) acc_s[j][3] = -1e30f;
            }
        }

        float mx0 = -1e30f, mx1 = -1e30f;
#pragma unroll
        for (int j = 0; j < 8; ++j) {
            mx0 = fmaxf(mx0, fmaxf(acc_s[j][0], acc_s[j][1]));
            mx1 = fmaxf(mx1, fmaxf(acc_s[j][2], acc_s[j][3]));
        }
        mx0 = fmaxf(mx0, __shfl_xor_sync(0xffffffffu, mx0, 1));
        mx0 = fmaxf(mx0, __shfl_xor_sync(0xffffffffu, mx0, 2));
        mx1 = fmaxf(mx1, __shfl_xor_sync(0xffffffffu, mx1, 1));
        mx1 = fmaxf(mx1, __shfl_xor_sync(0xffffffffu, mx1, 2));
        const float mn0 = fmaxf(m0, mx0), mn1 = fmaxf(m1, mx1);
        const float f0  = exp2p((m0 - mn0) * LOG2E);
        const float f1  = exp2p((m1 - mn1) * LOG2E);
        m0 = mn0; m1 = mn1;

        float s0 = 0.0f, s1 = 0.0f;
#pragma unroll
        for (int j = 0; j < 8; ++j) {
            acc_s[j][0] = exp2p((acc_s[j][0] - mn0) * LOG2E);
            acc_s[j][1] = exp2p((acc_s[j][1] - mn0) * LOG2E);
            acc_s[j][2] = exp2p((acc_s[j][2] - mn1) * LOG2E);
            acc_s[j][3] = exp2p((acc_s[j][3] - mn1) * LOG2E);
            s0 += acc_s[j][0] + acc_s[j][1];
            s1 += acc_s[j][2] + acc_s[j][3];
        }
        s0 += __shfl_xor_sync(0xffffffffu, s0, 1);
        s0 += __shfl_xor_sync(0xffffffffu, s0, 2);
        s1 += __shfl_xor_sync(0xffffffffu, s1, 1);
        s1 += __shfl_xor_sync(0xffffffffu, s1, 2);
        l0 = l0 * f0 + s0;
        l1 = l1 * f1 + s1;
#pragma unroll
        for (int j = 0; j < 8; ++j) {
            acc_o[j][0] *= f0; acc_o[j][1] *= f0;
            acc_o[j][2] *= f1; acc_o[j][3] *= f1;
        }

        uint32_t aPh[4][4];
#pragma unroll
        for (int t = 0; t < 4; ++t) {
            aPh[t][0] = pack_bf2(acc_s[2 * t][0],     acc_s[2 * t][1]);
            aPh[t][1] = pack_bf2(acc_s[2 * t][2],     acc_s[2 * t][3]);
            aPh[t][2] = pack_bf2(acc_s[2 * t + 1][0], acc_s[2 * t + 1][1]);
            aPh[t][3] = pack_bf2(acc_s[2 * t + 1][2], acc_s[2 * t + 1][3]);
        }
        bpass(acc_o, aPh, Vb, 0,  rbase, bch);
        bpass(acc_o, aPh, Vb, 64, rbase, bch);
        uint32_t aPl[4][4];
#pragma unroll
        for (int t = 0; t < 4; ++t) {
            aPl[t][0] = pack_bf2(acc_s[2 * t][0] - bhi(acc_s[2 * t][0]),
                                 acc_s[2 * t][1] - bhi(acc_s[2 * t][1]));
            aPl[t][1] = pack_bf2(acc_s[2 * t][2] - bhi(acc_s[2 * t][2]),
                                 acc_s[2 * t][3] - bhi(acc_s[2 * t][3]));
            aPl[t][2] = pack_bf2(acc_s[2 * t + 1][0] - bhi(acc_s[2 * t + 1][0]),
                                 acc_s[2 * t + 1][1] - bhi(acc_s[2 * t + 1][1]));
            aPl[t][3] = pack_bf2(acc_s[2 * t + 1][2] - bhi(acc_s[2 * t + 1][2]),
                                 acc_s[2 * t + 1][3] - bhi(acc_s[2 * t + 1][3]));
        }
        bpass(acc_o, aPl, Vb, 0, rbase, bch);
    }

    const int b   = bh >> 4;
    const int h   = bh & 15;
    const float inv0 = 1.0f / l0, inv1 = 1.0f / l1;
#pragma unroll
    for (int j = 0; j < 8; ++j) {
        const int d = j * 8 + tig * 2;
#pragma unroll
        for (int h2 = 0; h2 < 2; ++h2) {
            const int   rr  = (h2 ? row1 : row0);
            const float inv = (h2 ? inv1 : inv0);
            const float v0  = acc_o[j][h2 * 2]     * inv;
            const float v1  = acc_o[j][h2 * 2 + 1] * inv;
            const __nv_bfloat16 h0 = __float2bfloat16(v0);
            const __nv_bfloat16 h1 = __float2bfloat16(v1);
            const uint32_t hu = ((uint32_t)__bfloat16_as_ushort(h1) << 16)
                              | __bfloat16_as_ushort(h0);
            const uint32_t lu = pack_bf2(v0 - __bfloat162float(h0),
                                         v1 - __bfloat162float(h1));
            __nv_bfloat16* ap = Aout + ((size_t)b * SEQ + rr) * KP + h * HDIM + d;
            *(uint32_t*)(ap)        = hu;
            *(uint32_t*)(ap + 1024) = hu;
            *(uint32_t*)(ap + 2048) = lu;
        }
    }
}

// ---------------------------------------------------------------------------
extern "C" void kernel_launch(void* const* d_in, const int* in_sizes, int n_in,
                              void* d_out, int out_size)
{
    const float* x  = (const float*)d_in[0];
    const float* Wq = (const float*)d_in[1];
    const float* Wk = (const float*)d_in[2];
    const float* Wv = (const float*)d_in[3];
    const float* Wo = (const float*)d_in[4];
    float* out = (float*)d_out;

    float *k, *v;
    __nv_bfloat16 *ax, *bqkv, *bo, *aatt, *qp, *kp, *vp;
    cudaGetSymbolAddress((void**)&k,    g_K);
    cudaGetSymbolAddress((void**)&v,    g_V);
    cudaGetSymbolAddress((void**)&ax,   g_Ax);
    cudaGetSymbolAddress((void**)&bqkv, g_Bqkv);
    cudaGetSymbolAddress((void**)&bo,   g_Bo);
    cudaGetSymbolAddress((void**)&aatt, g_Aatt);
    cudaGetSymbolAddress((void**)&qp,   g_Qp);
    cudaGetSymbolAddress((void**)&kp,   g_Kp);
    cudaGetSymbolAddress((void**)&vp,   g_Vp);

    split_x<<<MTOT, 256>>>(x, ax);
    split_w<<<dim3(D_MODEL, 4), 256>>>(Wq, Wk, Wv, Wo, bqkv, bo);

    cudaFuncSetAttribute(gemm_mma,
                         cudaFuncAttributeMaxDynamicSharedMemorySize, SMEM_BYTES);

    // fused QKV: N = 3072; Q third writes g_Qp directly (split, scaled)
    gemm_mma<<<dim3(3 * D_MODEL / 128, MTOT / 128), 128, SMEM_BYTES>>>(
        ax, bqkv, qp, k, v, 1);

    conv_kv<<<dim3(32, 32, 2), 128>>>(k, v, kp, vp);

    cudaFuncSetAttribute(attn_fa2,
                         cudaFuncAttributeMaxDynamicSharedMemorySize, 65536);
    attn_fa2<<<dim3(SEQ / 64, BATCH * NHEAD), 128, 65536>>>(aatt, qp, kp, vp);

    gemm_mma<<<dim3(D_MODEL / 128, MTOT / 128), 128, SMEM_BYTES>>>(
        aatt, bo, out, out, out, 0);
}

// round 17
// speedup vs baseline: 1.0386x; 1.0386x over previous
#include <cuda_runtime.h>
#include <cuda_bf16.h>
#include <math.h>
#include <stdint.h>

#define D_MODEL 1024
#define NHEAD   16
#define HDIM    64
#define SEQ     2048
#define BATCH   2
#define MTOT    (BATCH * SEQ)   // 4096
#define KP      3072            // split-bf16 K' = 3*1024
#define TK      64              // bf16 per K chunk (128 bytes)
#define NC      (KP / TK)       // 48 chunks
#define LOG2E   1.4426950408889634f

// ---------------- scratch (static device globals: allocation-free) ----------
__device__ float g_V[BATCH * NHEAD * SEQ * HDIM];   // [b,h,s,d] fp32
__device__ __nv_bfloat16 g_Ax[MTOT * KP];           // split x    (A-mode)
__device__ __nv_bfloat16 g_Bqkv[3 * D_MODEL * KP];  // split Wq|Wk|Wv (B-mode)
__device__ __nv_bfloat16 g_Bo[D_MODEL * KP];
__device__ __nv_bfloat16 g_Aatt[MTOT * KP];         // split attn out (A-mode)
// attention operands, preconverted:
__device__ __nv_bfloat16 g_Qp[32 * SEQ * 128];          // [bh*2048+s][qh|ql]
__device__ __nv_bfloat16 g_Kp[32 * 32 * 64 * 128];      // [bh][kt] 16KB swizzled
__device__ __nv_bfloat16 g_Vp[32 * 32 * 64 * 128];      // [bh][kt] 16KB swizzled

// ============================ helpers ========================================
__device__ __forceinline__ uint32_t smem_u32(const void* p) {
    uint32_t a;
    asm("{ .reg .u64 t; cvta.to.shared.u64 t, %1; cvt.u32.u64 %0, t; }"
        : "=r"(a) : "l"(p));
    return a;
}
__device__ __forceinline__ void ldsm4(uint32_t* r, uint32_t addr) {
    asm volatile("ldmatrix.sync.aligned.m8n8.x4.shared.b16 {%0,%1,%2,%3}, [%4];"
                 : "=r"(r[0]), "=r"(r[1]), "=r"(r[2]), "=r"(r[3]) : "r"(addr));
}
__device__ __forceinline__ void mma16816(float* d, const uint32_t* a,
                                         const uint32_t* b) {
    asm volatile(
        "mma.sync.aligned.m16n8k16.row.col.f32.bf16.bf16.f32 "
        "{%0,%1,%2,%3}, {%4,%5,%6,%7}, {%8,%9}, {%0,%1,%2,%3};"
        : "+f"(d[0]), "+f"(d[1]), "+f"(d[2]), "+f"(d[3])
        : "r"(a[0]), "r"(a[1]), "r"(a[2]), "r"(a[3]), "r"(b[0]), "r"(b[1]));
}
__device__ __forceinline__ void cpa16(uint32_t dst, const void* src) {
    asm volatile("cp.async.cg.shared.global [%0], [%1], 16;"
                 :: "r"(dst), "l"(src));
}
#define CP_COMMIT() asm volatile("cp.async.commit_group;")
#define CP_WAIT0()  asm volatile("cp.async.wait_group 0;")
#define CP_WAIT1()  asm volatile("cp.async.wait_group 1;")

// 2^y on the FMA pipe; clamped so -huge -> ~1e-38 (≈0)
__device__ __forceinline__ float exp2p(float y) {
    y = fmaxf(y, -126.0f);
    const int   ni = __float2int_rn(y);
    const float f  = y - (float)ni;
    float p = 0.0096181f;
    p = fmaf(p, f, 0.0555041f);
    p = fmaf(p, f, 0.2402265f);
    p = fmaf(p, f, 0.6931472f);
    p = fmaf(p, f, 1.0f);
    return __int_as_float(__float_as_int(p) + (ni << 23));
}
__device__ __forceinline__ uint32_t pack_bf2(float a, float b) {
    return ((uint32_t)__bfloat16_as_ushort(__float2bfloat16(b)) << 16)
         | __bfloat16_as_ushort(__float2bfloat16(a));
}
__device__ __forceinline__ float bhi(float x) {
    return __bfloat162float(__float2bfloat16(x));
}
// byte offset in a 256B-row (128 bf16 col) XOR-swizzled tile
__device__ __forceinline__ uint32_t sw256(int row, int col) {
    return (uint32_t)(row * 256 + ((col >> 6) << 7)
                      + ((((col >> 3) & 7) ^ (row & 7)) << 4) + (col & 7) * 2);
}

// ============================ split kernels ==================================
__device__ __forceinline__ void split_row(const float* __restrict__ src,
                                          __nv_bfloat16* __restrict__ dst,
                                          int idx, int bmode)
{
    const int row = idx >> 8;
    const int c   = (idx & 255) * 4;
    float4 v = *(const float4*)(src + (size_t)row * 1024 + c);

    __nv_bfloat16 h0 = __float2bfloat16(v.x), h1 = __float2bfloat16(v.y);
    __nv_bfloat16 h2 = __float2bfloat16(v.z), h3 = __float2bfloat16(v.w);
    uint2 hu, lu;
    hu.x = ((uint32_t)__bfloat16_as_ushort(h1) << 16) | __bfloat16_as_ushort(h0);
    hu.y = ((uint32_t)__bfloat16_as_ushort(h3) << 16) | __bfloat16_as_ushort(h2);
    lu.x = pack_bf2(v.x - __bfloat162float(h0), v.y - __bfloat162float(h1));
    lu.y = pack_bf2(v.z - __bfloat162float(h2), v.w - __bfloat162float(h3));

    __nv_bfloat16* p = dst + (size_t)row * KP + c;
    if (bmode) {
        *(uint2*)(p) = hu; *(uint2*)(p + 1024) = lu; *(uint2*)(p + 2048) = hu;
    } else {
        *(uint2*)(p) = hu; *(uint2*)(p + 1024) = hu; *(uint2*)(p + 2048) = lu;
    }
}
__global__ __launch_bounds__(256) void split_x(
    const float* __restrict__ src, __nv_bfloat16* __restrict__ dst)
{
    split_row(src, dst, blockIdx.x * 256 + threadIdx.x, 0);
}
__global__ __launch_bounds__(256) void split_w(
    const float* __restrict__ w0, const float* __restrict__ w1,
    const float* __restrict__ w2, const float* __restrict__ w3,
    __nv_bfloat16* __restrict__ dqkv, __nv_bfloat16* __restrict__ do_)
{
    const int y = blockIdx.y;
    const float* src = (y == 0) ? w0 : (y == 1) ? w1 : (y == 2) ? w2 : w3;
    __nv_bfloat16* dst = (y == 3) ? do_ : dqkv + (size_t)y * 1024 * KP;
    split_row(src, dst, blockIdx.x * 256 + threadIdx.x, 1);
}

// ============== mma.sync GEMM: 3-stage cp.async, 1 sync/chunk ================
// mode 0: C0 = fp32 row-major [m][1024]           (N = 1024 launch)
// mode 1: fused QKV, which = bn>>10:
//         which 0 -> C0 = g_Qp  (bf16 split rows, scaled 1/8, direct)
//         which 1 -> C1 = g_Kp  (bf16 split swizzled tiles, direct)
//         which 2 -> C2 = g_V   (fp32 [b,h,s,d])
#define SMEM_BYTES 98304   // 3 stages x (A 16K + B 16K)

__device__ __forceinline__ void cpa_tiles(
    const __nv_bfloat16* __restrict__ A, const __nv_bfloat16* __restrict__ B,
    int bm, int bn, int c, int tid, uint32_t sbase, uint32_t p)
{
    const uint32_t Ab = sbase + p * 32768u;
#pragma unroll
    for (int j = 0; j < 4; ++j) {
        const int idx = j * 256 + tid, r = idx >> 3, s = idx & 7;
        uint32_t off = (uint32_t)(r * 128 + s * 16);
        off ^= (off >> 3) & 0x70;
        cpa16(Ab + off,           A + (size_t)(bm + r) * KP + c * TK + s * 8);
        cpa16(Ab + 16384u + off,  B + (size_t)(bn + r) * KP + c * TK + s * 8);
    }
    CP_COMMIT();
}

__global__ __launch_bounds__(256, 2) void gemm_mma(
    const __nv_bfloat16* __restrict__ A, const __nv_bfloat16* __restrict__ B,
    void* __restrict__ C0, void* __restrict__ C1, float* __restrict__ C2,
    int mode)
{
    extern __shared__ char smem[];
    const uint32_t sbase = smem_u32(smem);
    const int tid  = threadIdx.x;
    const int warp = tid >> 5;
    const int lane = tid & 31;
    const int bm   = blockIdx.y * 128;
    const int bn   = blockIdx.x * 128;
    const int wm   = warp & 1;
    const int wn   = warp >> 1;

    cpa_tiles(A, B, bm, bn, 0, tid, sbase, 0);
    cpa_tiles(A, B, bm, bn, 1, tid, sbase, 1);

    float acc[4][4][4];
#pragma unroll
    for (int i = 0; i < 4; ++i)
#pragma unroll
        for (int j = 0; j < 4; ++j)
#pragma unroll
            for (int r = 0; r < 4; ++r) acc[i][j][r] = 0.0f;

    const int arow = (lane & 7) | ((lane >> 3) & 1) << 3;
    const int ach  = (lane >> 4) & 1;
    uint32_t aterm[4]; int asw[4];
#pragma unroll
    for (int i = 0; i < 4; ++i) {
        const int row = wm * 64 + i * 16 + arow;
        aterm[i] = (uint32_t)(row * 128);
        asw[i]   = row & 7;
    }
    const int q   = lane >> 3;
    const int bch = q & 1;
    uint32_t bterm[2]; int bsw[2];
#pragma unroll
    for (int jj = 0; jj < 2; ++jj) {
        const int nrow = wn * 32 + jj * 16 + ((q >> 1) << 3) + (lane & 7);
        bterm[jj] = (uint32_t)(nrow * 128);
        bsw[jj]   = nrow & 7;
    }

    int p = 0;
    int pn = 2;
    for (int c = 0; c < NC; ++c) {
        if (c < NC - 1) { CP_WAIT1(); } else { CP_WAIT0(); }
        __syncthreads();

        if (c + 2 < NC) cpa_tiles(A, B, bm, bn, c + 2, tid, sbase, (uint32_t)pn);

        const uint32_t Ab = sbase + (uint32_t)(p * 32768);
        const uint32_t Bb = Ab + 16384u;

#pragma unroll
        for (int ks = 0; ks < 4; ++ks) {
            const int k2 = ks * 2;
            uint32_t af[4][4], bf[4][2];
#pragma unroll
            for (int i = 0; i < 4; ++i)
                ldsm4(af[i], Ab + aterm[i] + ((uint32_t)((k2 + ach) ^ asw[i]) << 4));
#pragma unroll
            for (int jj = 0; jj < 2; ++jj) {
                uint32_t t[4];
                ldsm4(t, Bb + bterm[jj] + ((uint32_t)((k2 + bch) ^ bsw[jj]) << 4));
                bf[jj * 2 + 0][0] = t[0]; bf[jj * 2 + 0][1] = t[1];
                bf[jj * 2 + 1][0] = t[2]; bf[jj * 2 + 1][1] = t[3];
            }
#pragma unroll
            for (int i = 0; i < 4; ++i)
#pragma unroll
                for (int j = 0; j < 4; ++j)
                    mma16816(acc[i][j], af[i], bf[j]);
        }

        p  = (p  == 2) ? 0 : p  + 1;
        pn = (pn == 2) ? 0 : pn + 1;
    }

    const int g   = lane >> 2;
    const int tig = lane & 3;
    const int which = (mode == 1) ? (bn >> 10) : 0;
#pragma unroll
    for (int i = 0; i < 4; ++i) {
#pragma unroll
        for (int j = 0; j < 4; ++j) {
            const int col = bn + wn * 32 + j * 8 + tig * 2;
            const int m0  = bm + wm * 64 + i * 16 + g;
#pragma unroll
            for (int hrow = 0; hrow < 2; ++hrow) {
                const int m = m0 + hrow * 8;
                float v0 = acc[i][j][hrow * 2];
                float v1 = acc[i][j][hrow * 2 + 1];
                if (mode == 0) {
                    *(float2*)((float*)C0 + (size_t)m * D_MODEL + col) =
                        make_float2(v0, v1);
                    continue;
                }
                const int b = m >> 11, s2 = m & 2047;
                const int cq = col & 1023;
                const int h = cq >> 6, dd = cq & 63;
                if (which == 2) {
                    *(float2*)(C2 + ((((size_t)b * NHEAD + h) * SEQ + s2) * HDIM + dd)) =
                        make_float2(v0, v1);
                    continue;
                }
                if (which == 0) { v0 *= 0.125f; v1 *= 0.125f; }
                const __nv_bfloat16 h0 = __float2bfloat16(v0);
                const __nv_bfloat16 h1 = __float2bfloat16(v1);
                const uint32_t hu = ((uint32_t)__bfloat16_as_ushort(h1) << 16)
                                  | __bfloat16_as_ushort(h0);
                const uint32_t lu = pack_bf2(v0 - __bfloat162float(h0),
                                             v1 - __bfloat162float(h1));
                if (which == 0) {
                    __nv_bfloat16* qp = (__nv_bfloat16*)C0
                        + ((size_t)(b * NHEAD + h) * SEQ + s2) * 128;
                    *(uint32_t*)(qp + dd)      = hu;
                    *(uint32_t*)(qp + 64 + dd) = lu;
                } else {   // which == 1: K' swizzled tile, direct
                    char* tb = (char*)C1
                        + ((size_t)(b * NHEAD + h) * 32 + (s2 >> 6)) * 16384;
                    const int key = s2 & 63;
                    *(uint32_t*)(tb + sw256(key, dd))      = hu;
                    *(uint32_t*)(tb + sw256(key, 64 + dd)) = lu;
                }
            }
        }
    }
}

// =================== V' pre-convert (smem-staged transpose) ==================
__global__ __launch_bounds__(128) void conv_v(const float* __restrict__ Vg,
                                              __nv_bfloat16* __restrict__ Vp)
{
    __shared__ float ts[64][65];
    const int bh = blockIdx.y, kt = blockIdx.x, tid = threadIdx.x;
    char* dst = (char*)(Vp + ((size_t)bh * 32 + kt) * 8192);
    {
        const int key = tid >> 1, d0 = (tid & 1) * 32;
        const float* src = Vg + (((size_t)bh * SEQ) + kt * 64 + key) * 64 + d0;
#pragma unroll
        for (int g4 = 0; g4 < 32; g4 += 4) {
            const float4 a = *(const float4*)(src + g4);
            ts[d0 + g4 + 0][key] = a.x;
            ts[d0 + g4 + 1][key] = a.y;
            ts[d0 + g4 + 2][key] = a.z;
            ts[d0 + g4 + 3][key] = a.w;
        }
    }
    __syncthreads();
    {
        const int d = tid >> 1, k0 = (tid & 1) * 32;
#pragma unroll
        for (int g8 = 0; g8 < 32; g8 += 8) {
            float v[8];
#pragma unroll
            for (int u = 0; u < 8; ++u) v[u] = ts[d][k0 + g8 + u];
            uint4 hu, lu;
            const __nv_bfloat16 h0 = __float2bfloat16(v[0]), h1 = __float2bfloat16(v[1]);
            const __nv_bfloat16 h2 = __float2bfloat16(v[2]), h3 = __float2bfloat16(v[3]);
            const __nv_bfloat16 h4 = __float2bfloat16(v[4]), h5 = __float2bfloat16(v[5]);
            const __nv_bfloat16 h6 = __float2bfloat16(v[6]), h7 = __float2bfloat16(v[7]);
            hu.x = ((uint32_t)__bfloat16_as_ushort(h1) << 16) | __bfloat16_as_ushort(h0);
            hu.y = ((uint32_t)__bfloat16_as_ushort(h3) << 16) | __bfloat16_as_ushort(h2);
            hu.z = ((uint32_t)__bfloat16_as_ushort(h5) << 16) | __bfloat16_as_ushort(h4);
            hu.w = ((uint32_t)__bfloat16_as_ushort(h7) << 16) | __bfloat16_as_ushort(h6);
            lu.x = pack_bf2(v[0] - __bfloat162float(h0), v[1] - __bfloat162float(h1));
            lu.y = pack_bf2(v[2] - __bfloat162float(h2), v[3] - __bfloat162float(h3));
            lu.z = pack_bf2(v[4] - __bfloat162float(h4), v[5] - __bfloat162float(h5));
            lu.w = pack_bf2(v[6] - __bfloat162float(h6), v[7] - __bfloat162float(h7));
            *(uint4*)(dst + sw256(d, k0 + g8))      = hu;
            *(uint4*)(dst + sw256(d, 64 + k0 + g8)) = lu;
        }
    }
}

// ======================= FA2 tensor-core attention (R12, validated) ==========
__device__ __forceinline__ void bpass(
    float acc[8][4], const uint32_t a[4][4], uint32_t bufu, int segcol,
    int rbase, int bch)
{
#pragma unroll
    for (int t = 0; t < 4; ++t) {
        uint32_t bf[8][2];
#pragma unroll
        for (int jj = 0; jj < 4; ++jj) {
            uint32_t bt[4];
            ldsm4(bt, bufu + sw256(jj * 16 + rbase, segcol + t * 16 + bch * 8));
            bf[jj * 2 + 0][0] = bt[0]; bf[jj * 2 + 0][1] = bt[1];
            bf[jj * 2 + 1][0] = bt[2]; bf[jj * 2 + 1][1] = bt[3];
        }
#pragma unroll
        for (int j = 0; j < 8; ++j) mma16816(acc[j], a[t], bf[j]);
    }
}

__global__ __launch_bounds__(128) void attn_fa2(
    __nv_bfloat16* __restrict__ Aout,
    const __nv_bfloat16* __restrict__ Qp,
    const __nv_bfloat16* __restrict__ Kp,
    const __nv_bfloat16* __restrict__ Vp)
{
    extern __shared__ char sm[];
    const uint32_t sbase = smem_u32(sm);
    const int tid  = threadIdx.x;
    const int warp = tid >> 5;
    const int lane = tid & 31;
    const int bh   = blockIdx.y;
    const int qt   = (int)gridDim.x - 1 - (int)blockIdx.x;   // heavy first
    const int q0   = qt * 64;
    const int ktmax = qt;

    {
        const char* ksrc = (const char*)(Kp + ((size_t)bh * 32) * 8192);
        const char* vsrc = (const char*)(Vp + ((size_t)bh * 32) * 8192);
#pragma unroll
        for (int i = 0; i < 8; ++i) {
            const uint32_t off = (uint32_t)(i * 2048 + tid * 16);
            cpa16(sbase + off, ksrc + off);
            cpa16(sbase + 16384u + off, vsrc + off);
        }
        CP_COMMIT();
    }

    const uint32_t stage = sbase + 32768u;
    {
        const __nv_bfloat16* qsrc = Qp + ((size_t)bh * SEQ + q0) * 128;
#pragma unroll
        for (int i = 0; i < 8; ++i) {
            const int c    = i * 128 + tid;
            const int row  = c >> 4;
            const int col8 = (c & 15) * 8;
            const uint4 v = *(const uint4*)(qsrc + (size_t)row * 128 + col8);
            *(uint4*)(sm + 32768 + sw256(row, col8)) = v;
        }
    }
    __syncthreads();

    const int arow  = (lane & 7) | (((lane >> 3) & 1) << 3);
    const int ach   = (lane >> 4) & 1;
    const int lq    = lane >> 3;
    const int bch   = lq & 1;
    const int rbase = ((lq >> 1) << 3) + (lane & 7);
    const int g     = lane >> 2;
    const int tig   = lane & 3;

    uint32_t aQh[4][4], aQl[4][4];
#pragma unroll
    for (int t = 0; t < 4; ++t) {
        ldsm4(aQh[t], stage + sw256(warp * 16 + arow, t * 16 + ach * 8));
        ldsm4(aQl[t], stage + sw256(warp * 16 + arow, 64 + t * 16 + ach * 8));
    }

    float acc_o[8][4];
#pragma unroll
    for (int j = 0; j < 8; ++j)
#pragma unroll
        for (int r = 0; r < 4; ++r) acc_o[j][r] = 0.0f;
    float m0 = -1e30f, m1 = -1e30f, l0 = 0.0f, l1 = 0.0f;

    const int row0 = q0 + warp * 16 + g;
    const int row1 = row0 + 8;

    for (int kt = 0; kt <= ktmax; ++kt) {
        CP_WAIT0();
        __syncthreads();

        if (kt < ktmax) {
            const char* ksrc = (const char*)(Kp + ((size_t)bh * 32 + kt + 1) * 8192);
            const char* vsrc = (const char*)(Vp + ((size_t)bh * 32 + kt + 1) * 8192);
            const uint32_t dst = sbase + (uint32_t)(((kt + 1) & 1) * 32768);
#pragma unroll
            for (int i = 0; i < 8; ++i) {
                const uint32_t off = (uint32_t)(i * 2048 + tid * 16);
                cpa16(dst + off, ksrc + off);
                cpa16(dst + 16384u + off, vsrc + off);
            }
            CP_COMMIT();
        }

        const uint32_t Kb = sbase + (uint32_t)((kt & 1) * 32768);
        const uint32_t Vb = Kb + 16384u;

        float acc_s[8][4];
#pragma unroll
        for (int j = 0; j < 8; ++j)
#pragma unroll
            for (int r = 0; r < 4; ++r) acc_s[j][r] = 0.0f;
        bpass(acc_s, aQh, Kb, 0,  rbase, bch);
        bpass(acc_s, aQh, Kb, 64, rbase, bch);
        bpass(acc_s, aQl, Kb, 0,  rbase, bch);

        if (kt * 64 + 63 > row0) {
#pragma unroll
            for (int j = 0; j < 8; ++j) {
                const int col = kt * 64 + j * 8 + tig * 2;
                if (col     > row0) acc_s[j][0] = -1e30f;
                if (col + 1 > row0) acc_s[j][1] = -1e30f;
                if (col     > row1) acc_s[j][2] = -1e30f;
                if (col + 1 > row1) acc_s[j][3] = -1e30f;
            }
        }

        float mx0 = -1e30f, mx1 = -1e30f;
#pragma unroll
        for (int j = 0; j < 8; ++j) {
            mx0 = fmaxf(mx0, fmaxf(acc_s[j][0], acc_s[j][1]));
            mx1 = fmaxf(mx1, fmaxf(acc_s[j][2], acc_s[j][3]));
        }
        mx0 = fmaxf(mx0, __shfl_xor_sync(0xffffffffu, mx0, 1));
        mx0 = fmaxf(mx0, __shfl_xor_sync(0xffffffffu, mx0, 2));
        mx1 = fmaxf(mx1, __shfl_xor_sync(0xffffffffu, mx1, 1));
        mx1 = fmaxf(mx1, __shfl_xor_sync(0xffffffffu, mx1, 2));
        const float mn0 = fmaxf(m0, mx0), mn1 = fmaxf(m1, mx1);
        const float f0  = exp2p((m0 - mn0) * LOG2E);
        const float f1  = exp2p((m1 - mn1) * LOG2E);
        m0 = mn0; m1 = mn1;

        float s0 = 0.0f, s1 = 0.0f;
#pragma unroll
        for (int j = 0; j < 8; ++j) {
            acc_s[j][0] = exp2p((acc_s[j][0] - mn0) * LOG2E);
            acc_s[j][1] = exp2p((acc_s[j][1] - mn0) * LOG2E);
            acc_s[j][2] = exp2p((acc_s[j][2] - mn1) * LOG2E);
            acc_s[j][3] = exp2p((acc_s[j][3] - mn1) * LOG2E);
            s0 += acc_s[j][0] + acc_s[j][1];
            s1 += acc_s[j][2] + acc_s[j][3];
        }
        s0 += __shfl_xor_sync(0xffffffffu, s0, 1);
        s0 += __shfl_xor_sync(0xffffffffu, s0, 2);
        s1 += __shfl_xor_sync(0xffffffffu, s1, 1);
        s1 += __shfl_xor_sync(0xffffffffu, s1, 2);
        l0 = l0 * f0 + s0;
        l1 = l1 * f1 + s1;
#pragma unroll
        for (int j = 0; j < 8; ++j) {
            acc_o[j][0] *= f0; acc_o[j][1] *= f0;
            acc_o[j][2] *= f1; acc_o[j][3] *= f1;
        }

        uint32_t aPh[4][4];
#pragma unroll
        for (int t = 0; t < 4; ++t) {
            aPh[t][0] = pack_bf2(acc_s[2 * t][0],     acc_s[2 * t][1]);
            aPh[t][1] = pack_bf2(acc_s[2 * t][2],     acc_s[2 * t][3]);
            aPh[t][2] = pack_bf2(acc_s[2 * t + 1][0], acc_s[2 * t + 1][1]);
            aPh[t][3] = pack_bf2(acc_s[2 * t + 1][2], acc_s[2 * t + 1][3]);
        }
        bpass(acc_o, aPh, Vb, 0,  rbase, bch);
        bpass(acc_o, aPh, Vb, 64, rbase, bch);
        uint32_t aPl[4][4];
#pragma unroll
        for (int t = 0; t < 4; ++t) {
            aPl[t][0] = pack_bf2(acc_s[2 * t][0] - bhi(acc_s[2 * t][0]),
                                 acc_s[2 * t][1] - bhi(acc_s[2 * t][1]));
            aPl[t][1] = pack_bf2(acc_s[2 * t][2] - bhi(acc_s[2 * t][2]),
                                 acc_s[2 * t][3] - bhi(acc_s[2 * t][3]));
            aPl[t][2] = pack_bf2(acc_s[2 * t + 1][0] - bhi(acc_s[2 * t + 1][0]),
                                 acc_s[2 * t + 1][1] - bhi(acc_s[2 * t + 1][1]));
            aPl[t][3] = pack_bf2(acc_s[2 * t + 1][2] - bhi(acc_s[2 * t + 1][2]),
                                 acc_s[2 * t + 1][3] - bhi(acc_s[2 * t + 1][3]));
        }
        bpass(acc_o, aPl, Vb, 0, rbase, bch);
    }

    const int b   = bh >> 4;
    const int h   = bh & 15;
    const float inv0 = 1.0f / l0, inv1 = 1.0f / l1;
#pragma unroll
    for (int j = 0; j < 8; ++j) {
        const int d = j * 8 + tig * 2;
#pragma unroll
        for (int h2 = 0; h2 < 2; ++h2) {
            const int   rr  = (h2 ? row1 : row0);
            const float inv = (h2 ? inv1 : inv0);
            const float v0  = acc_o[j][h2 * 2]     * inv;
            const float v1  = acc_o[j][h2 * 2 + 1] * inv;
            const __nv_bfloat16 h0 = __float2bfloat16(v0);
            const __nv_bfloat16 h1 = __float2bfloat16(v1);
            const uint32_t hu = ((uint32_t)__bfloat16_as_ushort(h1) << 16)
                              | __bfloat16_as_ushort(h0);
            const uint32_t lu = pack_bf2(v0 - __bfloat162float(h0),
                                         v1 - __bfloat162float(h1));
            __nv_bfloat16* ap = Aout + ((size_t)b * SEQ + rr) * KP + h * HDIM + d;
            *(uint32_t*)(ap)        = hu;
            *(uint32_t*)(ap + 1024) = hu;
            *(uint32_t*)(ap + 2048) = lu;
        }
    }
}

// ---------------------------------------------------------------------------
extern "C" void kernel_launch(void* const* d_in, const int* in_sizes, int n_in,
                              void* d_out, int out_size)
{
    const float* x  = (const float*)d_in[0];
    const float* Wq = (const float*)d_in[1];
    const float* Wk = (const float*)d_in[2];
    const float* Wv = (const float*)d_in[3];
    const float* Wo = (const float*)d_in[4];
    float* out = (float*)d_out;

    float *v;
    __nv_bfloat16 *ax, *bqkv, *bo, *aatt, *qp, *kp, *vp;
    cudaGetSymbolAddress((void**)&v,    g_V);
    cudaGetSymbolAddress((void**)&ax,   g_Ax);
    cudaGetSymbolAddress((void**)&bqkv, g_Bqkv);
    cudaGetSymbolAddress((void**)&bo,   g_Bo);
    cudaGetSymbolAddress((void**)&aatt, g_Aatt);
    cudaGetSymbolAddress((void**)&qp,   g_Qp);
    cudaGetSymbolAddress((void**)&kp,   g_Kp);
    cudaGetSymbolAddress((void**)&vp,   g_Vp);

    split_x<<<MTOT, 256>>>(x, ax);
    split_w<<<dim3(D_MODEL, 4), 256>>>(Wq, Wk, Wv, Wo, bqkv, bo);

    cudaFuncSetAttribute(gemm_mma,
                         cudaFuncAttributeMaxDynamicSharedMemorySize, SMEM_BYTES);

    // fused QKV: N = 3072; Q' and K' written directly (split bf16)
    gemm_mma<<<dim3(3 * D_MODEL / 128, MTOT / 128), 256, SMEM_BYTES>>>(
        ax, bqkv, qp, kp, v, 1);

    conv_v<<<dim3(32, 32), 128>>>(v, vp);

    cudaFuncSetAttribute(attn_fa2,
                         cudaFuncAttributeMaxDynamicSharedMemorySize, 65536);
    attn_fa2<<<dim3(SEQ / 64, BATCH * NHEAD), 128, 65536>>>(aatt, qp, kp, vp);

    gemm_mma<<<dim3(D_MODEL / 128, MTOT / 128), 256, SMEM_BYTES>>>(
        aatt, bo, out, out, out, 0);
}